// round 9
// baseline (speedup 1.0000x reference)
#include <cuda_runtime.h>
#include <cuda_fp16.h>
#include <mma.h>

using namespace nvcuda;

#define NMAX   100000
#define EMAX   1600000
#define CIN_   128
#define COUT_  64
#define SCAN_C 1024
#define NBLK_MAX 128

// Scratch (device globals — no allocation allowed).
// Invariants at entry (restored each call; static zero-init on first call):
//   g_deg == 0, g_scan_cnt == 0.
__device__ __half2 g_H2[NMAX * (COUT_ / 2)];   // Hs = (X@W+b)*dinv, fp16
__device__ float   g_dinv[NMAX];
__device__ int     g_deg[NMAX];
__device__ int     g_rowoff[NMAX];             // block-local exclusive prefix
__device__ int     g_boff[NBLK_MAX];           // per-1024-chunk global offset
__device__ int     g_bsum[NBLK_MAX];
__device__ int     g_pos[EMAX];
__device__ int     g_edge[EMAX];               // src only, CSR by dst
__device__ int     g_scan_cnt;

// ---------------------------------------------------------------------------
// 1) degree count + slot record, 4 edges/thread
// ---------------------------------------------------------------------------
__global__ __launch_bounds__(256) void degpos_kernel(const int* __restrict__ dst, int E) {
    int base = (blockIdx.x * 256 + threadIdx.x) * 4;
    if (base + 3 < E) {
        int4 d = *(const int4*)(dst + base);
        int4 p;
        p.x = atomicAdd(&g_deg[d.x], 1);
        p.y = atomicAdd(&g_deg[d.y], 1);
        p.z = atomicAdd(&g_deg[d.z], 1);
        p.w = atomicAdd(&g_deg[d.w], 1);
        *(int4*)(g_pos + base) = p;
    } else {
        for (int i = base; i < E; i++)
            g_pos[i] = atomicAdd(&g_deg[dst[i]], 1);
    }
}

// ---------------------------------------------------------------------------
// 2) scan: block-local exclusive prefix of deg, dinv=rsqrt(1+deg), deg:=0;
//    last-finishing block scans the <=128 block sums into g_boff.
// ---------------------------------------------------------------------------
__global__ __launch_bounds__(256) void scan_kernel(int n) {
    __shared__ int wsum[8];
    __shared__ int is_last;
    const int b    = blockIdx.x;
    const int base = b * SCAN_C + threadIdx.x * 4;
    const int lane = threadIdx.x & 31;
    const int warp = threadIdx.x >> 5;

    int v[4];
    #pragma unroll
    for (int i = 0; i < 4; i++) {
        int idx = base + i;
        v[i] = (idx < n) ? g_deg[idx] : 0;
        if (idx < n) {
            g_dinv[idx] = rsqrtf(1.0f + (float)v[i]);
            g_deg[idx]  = 0;                    // restore invariant
        }
    }
    int tsum = v[0] + v[1] + v[2] + v[3];

    int x = tsum;
    #pragma unroll
    for (int off = 1; off < 32; off <<= 1) {
        int y = __shfl_up_sync(0xFFFFFFFFu, x, off);
        if (lane >= off) x += y;
    }
    if (lane == 31) wsum[warp] = x;
    __syncthreads();
    if (threadIdx.x == 0) {
        int run = 0;
        #pragma unroll
        for (int w = 0; w < 8; w++) { int t = wsum[w]; wsum[w] = run; run += t; }
        g_bsum[b] = run;
    }
    __syncthreads();

    int run = wsum[warp] + x - tsum;
    #pragma unroll
    for (int i = 0; i < 4; i++) {
        int idx = base + i;
        if (idx < n) g_rowoff[idx] = run;
        run += v[i];
    }

    if (threadIdx.x == 0) {
        __threadfence();
        int old = atomicAdd(&g_scan_cnt, 1);
        is_last = (old == (int)gridDim.x - 1);
    }
    __syncthreads();
    if (is_last) {
        __threadfence();
        __shared__ int sp[NBLK_MAX];
        const int t = threadIdx.x;
        const int nblk = gridDim.x;
        if (t < NBLK_MAX) sp[t] = (t < nblk) ? g_bsum[t] : 0;
        __syncthreads();
        #pragma unroll
        for (int s = 1; s < NBLK_MAX; s <<= 1) {
            int vv = 0;
            if (t < NBLK_MAX && t >= s) vv = sp[t - s];
            __syncthreads();
            if (t < NBLK_MAX) sp[t] += vv;
            __syncthreads();
        }
        if (t < nblk) g_boff[t] = (t == 0) ? 0 : sp[t - 1];
        if (t == 0) g_scan_cnt = 0;             // restore invariant
    }
}

// ---------------------------------------------------------------------------
// 3) GEMM: Hs = (X @ W + b) * dinv — HMMA (wmma) with fp16 split precision:
//    X = Xh+Xl, W = Wh+Wl;  H ≈ Xh·Wh + Xl·Wh + Xh·Wl  (error ~2^-22)
//    Block: 256 threads = 8 warps; warp w owns rows w*16..w*16+15; 4 col
//    fragments cover 64 cols. k-tiles of 16. W split preloaded to smem.
// ---------------------------------------------------------------------------
__global__ __launch_bounds__(256) void gemm_kernel(
    const float* __restrict__ X, const float* __restrict__ W,
    const float* __restrict__ bias, int n)
{
    // smem layout (45,056 B):
    //   [0,      6144)  Xh  : half[128][24]
    //   [6144,  12288)  Xl  : half[128][24]
    //   [12288, 28672)  Wh  : half[128][64]
    //   [28672, 45056)  Wl  : half[128][64]
    //   [12288, 45056)  outbuf : float[128][64]  (aliases Wh/Wl, used post-loop)
    __shared__ __align__(16) unsigned char smem_raw[45056];
    __half (*Xh)[24] = reinterpret_cast<__half (*)[24]>(smem_raw);
    __half (*Xl)[24] = reinterpret_cast<__half (*)[24]>(smem_raw + 6144);
    __half (*Wh)[64] = reinterpret_cast<__half (*)[64]>(smem_raw + 12288);
    __half (*Wl)[64] = reinterpret_cast<__half (*)[64]>(smem_raw + 28672);
    float*  outbuf   = reinterpret_cast<float*>(smem_raw + 12288);

    const int tid  = threadIdx.x;
    const int wid  = tid >> 5;
    const int row0 = blockIdx.x * 128;

    // preload W, split into hi/lo halves
    for (int i = tid; i < CIN_ * COUT_; i += 256) {
        float w = W[i];
        __half h = __float2half_rn(w);
        __half l = __float2half_rn(w - __half2float(h));
        Wh[i >> 6][i & 63] = h;
        Wl[i >> 6][i & 63] = l;
    }

    wmma::fragment<wmma::accumulator, 16, 16, 16, float> acc[4];
    #pragma unroll
    for (int c = 0; c < 4; c++) wmma::fill_fragment(acc[c], 0.0f);

    const int xr = tid >> 1;            // 0..127
    const int xq = (tid & 1) * 8;       // 0 or 8

    for (int k0 = 0; k0 < CIN_; k0 += 16) {
        // load + split X tile: rows row0..row0+127, cols k0..k0+15
        {
            int rr = row0 + xr;
            const float* xp = X + (long)(rr < n ? rr : 0) * CIN_ + k0 + xq;
            float4 v0 = *(const float4*)xp;
            float4 v1 = *(const float4*)(xp + 4);
            float vv[8] = {v0.x, v0.y, v0.z, v0.w, v1.x, v1.y, v1.z, v1.w};
            #pragma unroll
            for (int i = 0; i < 8; i++) {
                __half h = __float2half_rn(vv[i]);
                __half l = __float2half_rn(vv[i] - __half2float(h));
                Xh[xr][xq + i] = h;
                Xl[xr][xq + i] = l;
            }
        }
        __syncthreads();

        wmma::fragment<wmma::matrix_a, 16, 16, 16, __half, wmma::row_major> ah, al;
        wmma::load_matrix_sync(ah, &Xh[wid * 16][0], 24);
        wmma::load_matrix_sync(al, &Xl[wid * 16][0], 24);
        #pragma unroll
        for (int c = 0; c < 4; c++) {
            wmma::fragment<wmma::matrix_b, 16, 16, 16, __half, wmma::row_major> bh, bl;
            wmma::load_matrix_sync(bh, &Wh[k0][c * 16], 64);
            wmma::load_matrix_sync(bl, &Wl[k0][c * 16], 64);
            wmma::mma_sync(acc[c], ah, bh, acc[c]);
            wmma::mma_sync(acc[c], al, bh, acc[c]);
            wmma::mma_sync(acc[c], ah, bl, acc[c]);
        }
        __syncthreads();
    }

    // stage fp32 results over the (now dead) W smem, then fused epilogue
    #pragma unroll
    for (int c = 0; c < 4; c++)
        wmma::store_matrix_sync(outbuf + (wid * 16) * 64 + c * 16, acc[c], 64,
                                wmma::mem_row_major);
    __syncthreads();

    for (int i = tid; i < 128 * 32; i += 256) {   // half2 elements
        int row = i >> 5;
        int cp  = i & 31;
        int grow = row0 + row;
        if (grow < n) {
            float2 v = *(float2*)(outbuf + row * 64 + cp * 2);
            float  di = g_dinv[grow];
            float2 bb = *(const float2*)(bias + cp * 2);
            g_H2[(long)grow * 32 + cp] =
                __floats2half2_rn((v.x + bb.x) * di, (v.y + bb.y) * di);
        }
    }
}

// ---------------------------------------------------------------------------
// 4) CSR fill (atomic-free, src-only payload), 4 edges/thread  [R7 form]
// ---------------------------------------------------------------------------
__global__ __launch_bounds__(256) void fill_kernel(
    const int* __restrict__ src, const int* __restrict__ dst, int E)
{
    int base = (blockIdx.x * 256 + threadIdx.x) * 4;
    if (base + 3 < E) {
        int4 s = *(const int4*)(src + base);
        int4 d = *(const int4*)(dst + base);
        int4 p = *(const int4*)(g_pos + base);
        int o0 = g_rowoff[d.x] + g_boff[d.x >> 10] + p.x;
        int o1 = g_rowoff[d.y] + g_boff[d.y >> 10] + p.y;
        int o2 = g_rowoff[d.z] + g_boff[d.z >> 10] + p.z;
        int o3 = g_rowoff[d.w] + g_boff[d.w >> 10] + p.w;
        g_edge[o0] = s.x;
        g_edge[o1] = s.y;
        g_edge[o2] = s.z;
        g_edge[o3] = s.w;
    } else {
        for (int i = base; i < E; i++) {
            int d = dst[i];
            g_edge[g_rowoff[d] + g_boff[d >> 10] + g_pos[i]] = src[i];
        }
    }
}

// ---------------------------------------------------------------------------
// 5) gather: one warp per node, one half2 per lane (64 cols), fp32 accum
//    out[d] = relu( dinv[d] * ( Hs[d] + sum_e Hs[src] ) )   [R7 form]
// ---------------------------------------------------------------------------
__device__ __forceinline__ float2 ldcs_h2f2(const __half2* p) {
    unsigned u;
    asm volatile("ld.global.cs.b32 %0, [%1];" : "=r"(u) : "l"(p));
    return __half22float2(*reinterpret_cast<__half2*>(&u));
}

__global__ __launch_bounds__(256) void gather_kernel(float* __restrict__ out,
                                                     int n, int E) {
    int node = (blockIdx.x * 256 + threadIdx.x) >> 5;
    if (node >= n) return;
    int lane = threadIdx.x & 31;

    float dd = g_dinv[node];
    int   r0 = g_rowoff[node] + g_boff[node >> 10];
    int   r1 = (node + 1 < n) ? (g_rowoff[node + 1] + g_boff[(node + 1) >> 10]) : E;
    int   m  = r1 - r0;

    float2 acc = __half22float2(g_H2[(long)node * 32 + lane]);

    const int* ep = &g_edge[r0];
    int j = 0;
    for (; j + 4 <= m; j += 4) {
        int e0 = __ldg(ep + j),     e1 = __ldg(ep + j + 1);
        int e2 = __ldg(ep + j + 2), e3 = __ldg(ep + j + 3);
        float2 h0 = ldcs_h2f2(&g_H2[(long)e0 * 32 + lane]);
        float2 h1 = ldcs_h2f2(&g_H2[(long)e1 * 32 + lane]);
        float2 h2 = ldcs_h2f2(&g_H2[(long)e2 * 32 + lane]);
        float2 h3 = ldcs_h2f2(&g_H2[(long)e3 * 32 + lane]);
        acc.x += h0.x + h1.x;  acc.y += h0.y + h1.y;
        acc.x += h2.x + h3.x;  acc.y += h2.y + h3.y;
    }
    for (; j < m; j++) {
        int e = __ldg(ep + j);
        float2 hh = ldcs_h2f2(&g_H2[(long)e * 32 + lane]);
        acc.x += hh.x;  acc.y += hh.y;
    }

    float2 o = make_float2(fmaxf(acc.x * dd, 0.0f), fmaxf(acc.y * dd, 0.0f));
    *(float2*)&out[(long)node * COUT_ + lane * 2] = o;
}

// ---------------------------------------------------------------------------
extern "C" void kernel_launch(void* const* d_in, const int* in_sizes, int n_in,
                              void* d_out, int out_size)
{
    const float* X    = (const float*)d_in[0];   // (N, 128)
    const float* W    = (const float*)d_in[1];   // (128, 64)
    const float* bias = (const float*)d_in[2];   // (64,)
    const int*   src  = (const int*)d_in[3];     // (E,)
    const int*   dst  = (const int*)d_in[4];     // (E,)
    float*       out  = (float*)d_out;           // (N, 64)

    const int n = in_sizes[0] / CIN_;
    const int E = in_sizes[3];
    const int nblk = (n + SCAN_C - 1) / SCAN_C;

    degpos_kernel<<<(E + 1023) / 1024, 256>>>(dst, E);
    scan_kernel<<<nblk, 256>>>(n);
    gemm_kernel<<<(n + 127) / 128, 256>>>(X, W, bias, n);
    fill_kernel<<<(E + 1023) / 1024, 256>>>(src, dst, E);
    gather_kernel<<<(int)(((long)n * 32 + 255) / 256), 256>>>(out, n, E);
}

// round 10
// speedup vs baseline: 1.1964x; 1.1964x over previous
#include <cuda_runtime.h>
#include <cuda_fp16.h>

#define NMAX   100000
#define EMAX   1600000
#define CIN_   128
#define COUT_  64
#define SCAN_C 1024
#define NBLK_MAX 128

// Scratch (device globals — no allocation allowed).
// Invariants at entry (restored each call; static zero-init on first call):
//   g_deg == 0, g_scan_cnt == 0.
__device__ __half2 g_H2[NMAX * (COUT_ / 2)];   // Hs = (X@W+b)*dinv, fp16
__device__ float   g_dinv[NMAX];
__device__ int     g_deg[NMAX];
__device__ int     g_rowoff[NMAX];             // block-local exclusive prefix
__device__ int     g_boff[NBLK_MAX];           // per-1024-chunk global offset
__device__ int     g_bsum[NBLK_MAX];
__device__ int     g_pos[EMAX];
__device__ int     g_edge[EMAX];               // src only, CSR by dst
__device__ int     g_scan_cnt;

// ---------------------------------------------------------------------------
// 1) degree count + slot record, 4 edges/thread
// ---------------------------------------------------------------------------
__global__ __launch_bounds__(256) void degpos_kernel(const int* __restrict__ dst, int E) {
    int base = (blockIdx.x * 256 + threadIdx.x) * 4;
    if (base + 3 < E) {
        int4 d = *(const int4*)(dst + base);
        int4 p;
        p.x = atomicAdd(&g_deg[d.x], 1);
        p.y = atomicAdd(&g_deg[d.y], 1);
        p.z = atomicAdd(&g_deg[d.z], 1);
        p.w = atomicAdd(&g_deg[d.w], 1);
        *(int4*)(g_pos + base) = p;
    } else {
        for (int i = base; i < E; i++)
            g_pos[i] = atomicAdd(&g_deg[dst[i]], 1);
    }
}

// ---------------------------------------------------------------------------
// 2) scan: block-local exclusive prefix of deg, dinv=rsqrt(1+deg), deg:=0;
//    last-finishing block scans the <=128 block sums into g_boff.
// ---------------------------------------------------------------------------
__global__ __launch_bounds__(256) void scan_kernel(int n) {
    __shared__ int wsum[8];
    __shared__ int is_last;
    const int b    = blockIdx.x;
    const int base = b * SCAN_C + threadIdx.x * 4;
    const int lane = threadIdx.x & 31;
    const int warp = threadIdx.x >> 5;

    int v[4];
    #pragma unroll
    for (int i = 0; i < 4; i++) {
        int idx = base + i;
        v[i] = (idx < n) ? g_deg[idx] : 0;
        if (idx < n) {
            g_dinv[idx] = rsqrtf(1.0f + (float)v[i]);
            g_deg[idx]  = 0;                    // restore invariant
        }
    }
    int tsum = v[0] + v[1] + v[2] + v[3];

    int x = tsum;
    #pragma unroll
    for (int off = 1; off < 32; off <<= 1) {
        int y = __shfl_up_sync(0xFFFFFFFFu, x, off);
        if (lane >= off) x += y;
    }
    if (lane == 31) wsum[warp] = x;
    __syncthreads();
    if (threadIdx.x == 0) {
        int run = 0;
        #pragma unroll
        for (int w = 0; w < 8; w++) { int t = wsum[w]; wsum[w] = run; run += t; }
        g_bsum[b] = run;
    }
    __syncthreads();

    int run = wsum[warp] + x - tsum;
    #pragma unroll
    for (int i = 0; i < 4; i++) {
        int idx = base + i;
        if (idx < n) g_rowoff[idx] = run;
        run += v[i];
    }

    if (threadIdx.x == 0) {
        __threadfence();
        int old = atomicAdd(&g_scan_cnt, 1);
        is_last = (old == (int)gridDim.x - 1);
    }
    __syncthreads();
    if (is_last) {
        __threadfence();
        __shared__ int sp[NBLK_MAX];
        const int t = threadIdx.x;
        const int nblk = gridDim.x;
        if (t < NBLK_MAX) sp[t] = (t < nblk) ? g_bsum[t] : 0;
        __syncthreads();
        #pragma unroll
        for (int s = 1; s < NBLK_MAX; s <<= 1) {
            int vv = 0;
            if (t < NBLK_MAX && t >= s) vv = sp[t - s];
            __syncthreads();
            if (t < NBLK_MAX) sp[t] += vv;
            __syncthreads();
        }
        if (t < nblk) g_boff[t] = (t == 0) ? 0 : sp[t - 1];
        if (t == 0) g_scan_cnt = 0;             // restore invariant
    }
}

// ---------------------------------------------------------------------------
// 3) GEMM: Hs = (X @ W + b) * dinv — packed fma.rn.f32x2, fp16 epilogue
//    [R7 measured-best form]
// ---------------------------------------------------------------------------
#define FMA2(d, a, b) asm("fma.rn.f32x2 %0, %1, %2, %3;" \
                          : "=l"(d) : "l"(a), "l"(b), "l"(d))

__global__ __launch_bounds__(256) void gemm_kernel(
    const float* __restrict__ X, const float* __restrict__ W,
    const float* __restrict__ bias, int n)
{
    __shared__ float2 Xs2[16][130];
    __shared__ float  Ws[16][64];

    const int tid  = threadIdx.x;
    const int tcol = tid & 15;
    const int trow = tid >> 4;
    const int row0 = blockIdx.x * 128;

    unsigned long long acc[8][2];
    #pragma unroll
    for (int r = 0; r < 8; r++) { acc[r][0] = 0ull; acc[r][1] = 0ull; }

    for (int k0 = 0; k0 < CIN_; k0 += 16) {
        #pragma unroll
        for (int p = 0; p < 2; p++) {
            int r  = p * 64 + (tid >> 2);
            int kq = tid & 3;
            int rr = row0 + r;
            const float* xp = X + (long)(rr < n ? rr : 0) * CIN_ + k0 + kq * 4;
            float4 v = *(const float4*)xp;
            Xs2[kq * 4 + 0][r] = make_float2(v.x, v.x);
            Xs2[kq * 4 + 1][r] = make_float2(v.y, v.y);
            Xs2[kq * 4 + 2][r] = make_float2(v.z, v.z);
            Xs2[kq * 4 + 3][r] = make_float2(v.w, v.w);
        }
        {
            int k    = tid >> 4;
            int colq = tid & 15;
            float4 v = *(const float4*)(W + (long)(k0 + k) * COUT_ + colq * 4);
            *(float4*)&Ws[k][colq * 4] = v;
        }
        __syncthreads();

        #pragma unroll
        for (int kk = 0; kk < 16; kk++) {
            ulonglong2 a01 = *(const ulonglong2*)&Xs2[kk][trow * 8 + 0];
            ulonglong2 a23 = *(const ulonglong2*)&Xs2[kk][trow * 8 + 2];
            ulonglong2 a45 = *(const ulonglong2*)&Xs2[kk][trow * 8 + 4];
            ulonglong2 a67 = *(const ulonglong2*)&Xs2[kk][trow * 8 + 6];
            ulonglong2 b   = *(const ulonglong2*)&Ws[kk][tcol * 4];
            FMA2(acc[0][0], a01.x, b.x);  FMA2(acc[0][1], a01.x, b.y);
            FMA2(acc[1][0], a01.y, b.x);  FMA2(acc[1][1], a01.y, b.y);
            FMA2(acc[2][0], a23.x, b.x);  FMA2(acc[2][1], a23.x, b.y);
            FMA2(acc[3][0], a23.y, b.x);  FMA2(acc[3][1], a23.y, b.y);
            FMA2(acc[4][0], a45.x, b.x);  FMA2(acc[4][1], a45.x, b.y);
            FMA2(acc[5][0], a45.y, b.x);  FMA2(acc[5][1], a45.y, b.y);
            FMA2(acc[6][0], a67.x, b.x);  FMA2(acc[6][1], a67.x, b.y);
            FMA2(acc[7][0], a67.y, b.x);  FMA2(acc[7][1], a67.y, b.y);
        }
        __syncthreads();
    }

    float2 bb0 = *(const float2*)(bias + tcol * 4);
    float2 bb1 = *(const float2*)(bias + tcol * 4 + 2);
    #pragma unroll
    for (int r = 0; r < 8; r++) {
        int row = row0 + trow * 8 + r;
        if (row < n) {
            float di = g_dinv[row];
            float2 lo = *(const float2*)&acc[r][0];
            float2 hi = *(const float2*)&acc[r][1];
            __half2 h0 = __floats2half2_rn((lo.x + bb0.x) * di, (lo.y + bb0.y) * di);
            __half2 h1 = __floats2half2_rn((hi.x + bb1.x) * di, (hi.y + bb1.y) * di);
            g_H2[(long)row * 32 + tcol * 2]     = h0;
            g_H2[(long)row * 32 + tcol * 2 + 1] = h1;
        }
    }
}

// ---------------------------------------------------------------------------
// 4) CSR fill (atomic-free, src-only payload), 4 edges/thread  [R7 form]
// ---------------------------------------------------------------------------
__global__ __launch_bounds__(256) void fill_kernel(
    const int* __restrict__ src, const int* __restrict__ dst, int E)
{
    int base = (blockIdx.x * 256 + threadIdx.x) * 4;
    if (base + 3 < E) {
        int4 s = *(const int4*)(src + base);
        int4 d = *(const int4*)(dst + base);
        int4 p = *(const int4*)(g_pos + base);
        int o0 = g_rowoff[d.x] + g_boff[d.x >> 10] + p.x;
        int o1 = g_rowoff[d.y] + g_boff[d.y >> 10] + p.y;
        int o2 = g_rowoff[d.z] + g_boff[d.z >> 10] + p.z;
        int o3 = g_rowoff[d.w] + g_boff[d.w >> 10] + p.w;
        g_edge[o0] = s.x;
        g_edge[o1] = s.y;
        g_edge[o2] = s.z;
        g_edge[o3] = s.w;
    } else {
        for (int i = base; i < E; i++) {
            int d = dst[i];
            g_edge[g_rowoff[d] + g_boff[d >> 10] + g_pos[i]] = src[i];
        }
    }
}

// ---------------------------------------------------------------------------
// 5) gather: one warp per node, one half2 per lane (64 cols), fp32 accum,
//    8 independent Hs-row loads in flight (MLP=8).
//    out[d] = relu( dinv[d] * ( Hs[d] + sum_e Hs[src] ) )
// ---------------------------------------------------------------------------
__device__ __forceinline__ float2 ldcs_h2f2(const __half2* p) {
    unsigned u;
    asm volatile("ld.global.cs.b32 %0, [%1];" : "=r"(u) : "l"(p));
    return __half22float2(*reinterpret_cast<__half2*>(&u));
}

__global__ __launch_bounds__(256) void gather_kernel(float* __restrict__ out,
                                                     int n, int E) {
    int node = (blockIdx.x * 256 + threadIdx.x) >> 5;
    if (node >= n) return;
    int lane = threadIdx.x & 31;

    float dd = g_dinv[node];
    int   r0 = g_rowoff[node] + g_boff[node >> 10];
    int   r1 = (node + 1 < n) ? (g_rowoff[node + 1] + g_boff[(node + 1) >> 10]) : E;
    int   m  = r1 - r0;

    float2 acc = __half22float2(g_H2[(long)node * 32 + lane]);

    const int* ep = &g_edge[r0];
    int j = 0;
    for (; j + 8 <= m; j += 8) {
        int e0 = __ldg(ep + j),     e1 = __ldg(ep + j + 1);
        int e2 = __ldg(ep + j + 2), e3 = __ldg(ep + j + 3);
        int e4 = __ldg(ep + j + 4), e5 = __ldg(ep + j + 5);
        int e6 = __ldg(ep + j + 6), e7 = __ldg(ep + j + 7);
        float2 h0 = ldcs_h2f2(&g_H2[(long)e0 * 32 + lane]);
        float2 h1 = ldcs_h2f2(&g_H2[(long)e1 * 32 + lane]);
        float2 h2 = ldcs_h2f2(&g_H2[(long)e2 * 32 + lane]);
        float2 h3 = ldcs_h2f2(&g_H2[(long)e3 * 32 + lane]);
        float2 h4 = ldcs_h2f2(&g_H2[(long)e4 * 32 + lane]);
        float2 h5 = ldcs_h2f2(&g_H2[(long)e5 * 32 + lane]);
        float2 h6 = ldcs_h2f2(&g_H2[(long)e6 * 32 + lane]);
        float2 h7 = ldcs_h2f2(&g_H2[(long)e7 * 32 + lane]);
        float sx = ((h0.x + h1.x) + (h2.x + h3.x)) + ((h4.x + h5.x) + (h6.x + h7.x));
        float sy = ((h0.y + h1.y) + (h2.y + h3.y)) + ((h4.y + h5.y) + (h6.y + h7.y));
        acc.x += sx;  acc.y += sy;
    }
    for (; j + 4 <= m; j += 4) {
        int e0 = __ldg(ep + j),     e1 = __ldg(ep + j + 1);
        int e2 = __ldg(ep + j + 2), e3 = __ldg(ep + j + 3);
        float2 h0 = ldcs_h2f2(&g_H2[(long)e0 * 32 + lane]);
        float2 h1 = ldcs_h2f2(&g_H2[(long)e1 * 32 + lane]);
        float2 h2 = ldcs_h2f2(&g_H2[(long)e2 * 32 + lane]);
        float2 h3 = ldcs_h2f2(&g_H2[(long)e3 * 32 + lane]);
        acc.x += (h0.x + h1.x) + (h2.x + h3.x);
        acc.y += (h0.y + h1.y) + (h2.y + h3.y);
    }
    for (; j < m; j++) {
        int e = __ldg(ep + j);
        float2 hh = ldcs_h2f2(&g_H2[(long)e * 32 + lane]);
        acc.x += hh.x;  acc.y += hh.y;
    }

    float2 o = make_float2(fmaxf(acc.x * dd, 0.0f), fmaxf(acc.y * dd, 0.0f));
    *(float2*)&out[(long)node * COUT_ + lane * 2] = o;
}

// ---------------------------------------------------------------------------
extern "C" void kernel_launch(void* const* d_in, const int* in_sizes, int n_in,
                              void* d_out, int out_size)
{
    const float* X    = (const float*)d_in[0];   // (N, 128)
    const float* W    = (const float*)d_in[1];   // (128, 64)
    const float* bias = (const float*)d_in[2];   // (64,)
    const int*   src  = (const int*)d_in[3];     // (E,)
    const int*   dst  = (const int*)d_in[4];     // (E,)
    float*       out  = (float*)d_out;           // (N, 64)

    const int n = in_sizes[0] / CIN_;
    const int E = in_sizes[3];
    const int nblk = (n + SCAN_C - 1) / SCAN_C;

    degpos_kernel<<<(E + 1023) / 1024, 256>>>(dst, E);
    scan_kernel<<<nblk, 256>>>(n);
    gemm_kernel<<<(n + 127) / 128, 256>>>(X, W, bias, n);
    fill_kernel<<<(E + 1023) / 1024, 256>>>(src, dst, E);
    gather_kernel<<<(int)(((long)n * 32 + 255) / 256), 256>>>(out, n, E);
}

// round 11
// speedup vs baseline: 1.3875x; 1.1597x over previous
#include <cuda_runtime.h>
#include <cuda_fp16.h>

#define NMAX   100000
#define EMAX   1600000
#define CIN_   128
#define COUT_  64
#define SCAN_C 1024
#define NBLK_MAX 128

// Scratch (device globals — no allocation allowed).
// Invariants at entry (restored each call; static zero-init on first call):
//   g_deg == 0, g_scan_cnt == 0.
__device__ __half2 g_H2[NMAX * (COUT_ / 2)];   // Hs = (X@W+b)*dinv, fp16
__device__ float   g_dinv[NMAX];
__device__ int     g_deg[NMAX];
__device__ int     g_rowoff[NMAX];             // block-local exclusive prefix
__device__ int     g_boff[NBLK_MAX];           // per-1024-chunk global offset
__device__ int     g_bsum[NBLK_MAX];
__device__ int     g_pos[EMAX];
__device__ int     g_edge[EMAX];               // src only, CSR by dst
__device__ int     g_scan_cnt;

// ---------------------------------------------------------------------------
// 1) degree count + slot record, 4 edges/thread
// ---------------------------------------------------------------------------
__global__ __launch_bounds__(256) void degpos_kernel(const int* __restrict__ dst, int E) {
    int base = (blockIdx.x * 256 + threadIdx.x) * 4;
    if (base + 3 < E) {
        int4 d = *(const int4*)(dst + base);
        int4 p;
        p.x = atomicAdd(&g_deg[d.x], 1);
        p.y = atomicAdd(&g_deg[d.y], 1);
        p.z = atomicAdd(&g_deg[d.z], 1);
        p.w = atomicAdd(&g_deg[d.w], 1);
        *(int4*)(g_pos + base) = p;
    } else {
        for (int i = base; i < E; i++)
            g_pos[i] = atomicAdd(&g_deg[dst[i]], 1);
    }
}

// ---------------------------------------------------------------------------
// 2) scan: block-local exclusive prefix of deg, dinv=rsqrt(1+deg), deg:=0;
//    last-finishing block scans the <=128 block sums into g_boff.
// ---------------------------------------------------------------------------
__global__ __launch_bounds__(256) void scan_kernel(int n) {
    __shared__ int wsum[8];
    __shared__ int is_last;
    const int b    = blockIdx.x;
    const int base = b * SCAN_C + threadIdx.x * 4;
    const int lane = threadIdx.x & 31;
    const int warp = threadIdx.x >> 5;

    int v[4];
    #pragma unroll
    for (int i = 0; i < 4; i++) {
        int idx = base + i;
        v[i] = (idx < n) ? g_deg[idx] : 0;
        if (idx < n) {
            g_dinv[idx] = rsqrtf(1.0f + (float)v[i]);
            g_deg[idx]  = 0;                    // restore invariant
        }
    }
    int tsum = v[0] + v[1] + v[2] + v[3];

    int x = tsum;
    #pragma unroll
    for (int off = 1; off < 32; off <<= 1) {
        int y = __shfl_up_sync(0xFFFFFFFFu, x, off);
        if (lane >= off) x += y;
    }
    if (lane == 31) wsum[warp] = x;
    __syncthreads();
    if (threadIdx.x == 0) {
        int run = 0;
        #pragma unroll
        for (int w = 0; w < 8; w++) { int t = wsum[w]; wsum[w] = run; run += t; }
        g_bsum[b] = run;
    }
    __syncthreads();

    int run = wsum[warp] + x - tsum;
    #pragma unroll
    for (int i = 0; i < 4; i++) {
        int idx = base + i;
        if (idx < n) g_rowoff[idx] = run;
        run += v[i];
    }

    if (threadIdx.x == 0) {
        __threadfence();
        int old = atomicAdd(&g_scan_cnt, 1);
        is_last = (old == (int)gridDim.x - 1);
    }
    __syncthreads();
    if (is_last) {
        __threadfence();
        __shared__ int sp[NBLK_MAX];
        const int t = threadIdx.x;
        const int nblk = gridDim.x;
        if (t < NBLK_MAX) sp[t] = (t < nblk) ? g_bsum[t] : 0;
        __syncthreads();
        #pragma unroll
        for (int s = 1; s < NBLK_MAX; s <<= 1) {
            int vv = 0;
            if (t < NBLK_MAX && t >= s) vv = sp[t - s];
            __syncthreads();
            if (t < NBLK_MAX) sp[t] += vv;
            __syncthreads();
        }
        if (t < nblk) g_boff[t] = (t == 0) ? 0 : sp[t - 1];
        if (t == 0) g_scan_cnt = 0;             // restore invariant
    }
}

// ---------------------------------------------------------------------------
// 3) fused GEMM + CSR fill, role split by block:
//    blocks [0, NG)      : GEMM tile (FMA pipe)   Hs = (X@W+b)*dinv, fp16
//    blocks [NG, NG+NF)  : fill chunk (LTS pipe)  edge[off(d)+pos] = src
//    Both depend only on degpos+scan; they are independent of each other.
// ---------------------------------------------------------------------------
#define FMA2(d, a, b) asm("fma.rn.f32x2 %0, %1, %2, %3;" \
                          : "=l"(d) : "l"(a), "l"(b), "l"(d))

__global__ __launch_bounds__(256) void gemmfill_kernel(
    const float* __restrict__ X, const float* __restrict__ W,
    const float* __restrict__ bias,
    const int* __restrict__ src, const int* __restrict__ dst,
    int n, int E, int NG)
{
    const int tid = threadIdx.x;

    if (blockIdx.x >= NG) {
        // ---- fill role (R7 measured-best body), 4 edges/thread ----
        int cid  = blockIdx.x - NG;
        int base = (cid * 256 + tid) * 4;
        if (base + 3 < E) {
            int4 s = *(const int4*)(src + base);
            int4 d = *(const int4*)(dst + base);
            int4 p = *(const int4*)(g_pos + base);
            int o0 = g_rowoff[d.x] + g_boff[d.x >> 10] + p.x;
            int o1 = g_rowoff[d.y] + g_boff[d.y >> 10] + p.y;
            int o2 = g_rowoff[d.z] + g_boff[d.z >> 10] + p.z;
            int o3 = g_rowoff[d.w] + g_boff[d.w >> 10] + p.w;
            g_edge[o0] = s.x;
            g_edge[o1] = s.y;
            g_edge[o2] = s.z;
            g_edge[o3] = s.w;
        } else {
            for (int i = base; i < E; i++) {
                int d = dst[i];
                g_edge[g_rowoff[d] + g_boff[d >> 10] + g_pos[i]] = src[i];
            }
        }
        return;
    }

    // ---- GEMM role (R7 measured-best body) ----
    __shared__ float2 Xs2[16][130];
    __shared__ float  Ws[16][64];

    const int tcol = tid & 15;
    const int trow = tid >> 4;
    const int row0 = blockIdx.x * 128;

    unsigned long long acc[8][2];
    #pragma unroll
    for (int r = 0; r < 8; r++) { acc[r][0] = 0ull; acc[r][1] = 0ull; }

    for (int k0 = 0; k0 < CIN_; k0 += 16) {
        #pragma unroll
        for (int p = 0; p < 2; p++) {
            int r  = p * 64 + (tid >> 2);
            int kq = tid & 3;
            int rr = row0 + r;
            const float* xp = X + (long)(rr < n ? rr : 0) * CIN_ + k0 + kq * 4;
            float4 v = *(const float4*)xp;
            Xs2[kq * 4 + 0][r] = make_float2(v.x, v.x);
            Xs2[kq * 4 + 1][r] = make_float2(v.y, v.y);
            Xs2[kq * 4 + 2][r] = make_float2(v.z, v.z);
            Xs2[kq * 4 + 3][r] = make_float2(v.w, v.w);
        }
        {
            int k    = tid >> 4;
            int colq = tid & 15;
            float4 v = *(const float4*)(W + (long)(k0 + k) * COUT_ + colq * 4);
            *(float4*)&Ws[k][colq * 4] = v;
        }
        __syncthreads();

        #pragma unroll
        for (int kk = 0; kk < 16; kk++) {
            ulonglong2 a01 = *(const ulonglong2*)&Xs2[kk][trow * 8 + 0];
            ulonglong2 a23 = *(const ulonglong2*)&Xs2[kk][trow * 8 + 2];
            ulonglong2 a45 = *(const ulonglong2*)&Xs2[kk][trow * 8 + 4];
            ulonglong2 a67 = *(const ulonglong2*)&Xs2[kk][trow * 8 + 6];
            ulonglong2 b   = *(const ulonglong2*)&Ws[kk][tcol * 4];
            FMA2(acc[0][0], a01.x, b.x);  FMA2(acc[0][1], a01.x, b.y);
            FMA2(acc[1][0], a01.y, b.x);  FMA2(acc[1][1], a01.y, b.y);
            FMA2(acc[2][0], a23.x, b.x);  FMA2(acc[2][1], a23.x, b.y);
            FMA2(acc[3][0], a23.y, b.x);  FMA2(acc[3][1], a23.y, b.y);
            FMA2(acc[4][0], a45.x, b.x);  FMA2(acc[4][1], a45.x, b.y);
            FMA2(acc[5][0], a45.y, b.x);  FMA2(acc[5][1], a45.y, b.y);
            FMA2(acc[6][0], a67.x, b.x);  FMA2(acc[6][1], a67.x, b.y);
            FMA2(acc[7][0], a67.y, b.x);  FMA2(acc[7][1], a67.y, b.y);
        }
        __syncthreads();
    }

    float2 bb0 = *(const float2*)(bias + tcol * 4);
    float2 bb1 = *(const float2*)(bias + tcol * 4 + 2);
    #pragma unroll
    for (int r = 0; r < 8; r++) {
        int row = row0 + trow * 8 + r;
        if (row < n) {
            float di = g_dinv[row];
            float2 lo = *(const float2*)&acc[r][0];
            float2 hi = *(const float2*)&acc[r][1];
            __half2 h0 = __floats2half2_rn((lo.x + bb0.x) * di, (lo.y + bb0.y) * di);
            __half2 h1 = __floats2half2_rn((hi.x + bb1.x) * di, (hi.y + bb1.y) * di);
            g_H2[(long)row * 32 + tcol * 2]     = h0;
            g_H2[(long)row * 32 + tcol * 2 + 1] = h1;
        }
    }
}

// ---------------------------------------------------------------------------
// 4) gather: one warp per node, one half2 per lane (64 cols), fp32 accum,
//    unroll-8, L1-cached loads (__ldg).
//    out[d] = relu( dinv[d] * ( Hs[d] + sum_e Hs[src] ) )
// ---------------------------------------------------------------------------
__device__ __forceinline__ float2 ldg_h2f2(const __half2* p) {
    return __half22float2(__ldg(p));
}

__global__ __launch_bounds__(256) void gather_kernel(float* __restrict__ out,
                                                     int n, int E) {
    int node = (blockIdx.x * 256 + threadIdx.x) >> 5;
    if (node >= n) return;
    int lane = threadIdx.x & 31;

    float dd = g_dinv[node];
    int   r0 = g_rowoff[node] + g_boff[node >> 10];
    int   r1 = (node + 1 < n) ? (g_rowoff[node + 1] + g_boff[(node + 1) >> 10]) : E;
    int   m  = r1 - r0;

    float2 acc = __half22float2(g_H2[(long)node * 32 + lane]);

    const int* ep = &g_edge[r0];
    int j = 0;
    for (; j + 8 <= m; j += 8) {
        int e0 = __ldg(ep + j),     e1 = __ldg(ep + j + 1);
        int e2 = __ldg(ep + j + 2), e3 = __ldg(ep + j + 3);
        int e4 = __ldg(ep + j + 4), e5 = __ldg(ep + j + 5);
        int e6 = __ldg(ep + j + 6), e7 = __ldg(ep + j + 7);
        float2 h0 = ldg_h2f2(&g_H2[(long)e0 * 32 + lane]);
        float2 h1 = ldg_h2f2(&g_H2[(long)e1 * 32 + lane]);
        float2 h2 = ldg_h2f2(&g_H2[(long)e2 * 32 + lane]);
        float2 h3 = ldg_h2f2(&g_H2[(long)e3 * 32 + lane]);
        float2 h4 = ldg_h2f2(&g_H2[(long)e4 * 32 + lane]);
        float2 h5 = ldg_h2f2(&g_H2[(long)e5 * 32 + lane]);
        float2 h6 = ldg_h2f2(&g_H2[(long)e6 * 32 + lane]);
        float2 h7 = ldg_h2f2(&g_H2[(long)e7 * 32 + lane]);
        float sx = ((h0.x + h1.x) + (h2.x + h3.x)) + ((h4.x + h5.x) + (h6.x + h7.x));
        float sy = ((h0.y + h1.y) + (h2.y + h3.y)) + ((h4.y + h5.y) + (h6.y + h7.y));
        acc.x += sx;  acc.y += sy;
    }
    for (; j + 4 <= m; j += 4) {
        int e0 = __ldg(ep + j),     e1 = __ldg(ep + j + 1);
        int e2 = __ldg(ep + j + 2), e3 = __ldg(ep + j + 3);
        float2 h0 = ldg_h2f2(&g_H2[(long)e0 * 32 + lane]);
        float2 h1 = ldg_h2f2(&g_H2[(long)e1 * 32 + lane]);
        float2 h2 = ldg_h2f2(&g_H2[(long)e2 * 32 + lane]);
        float2 h3 = ldg_h2f2(&g_H2[(long)e3 * 32 + lane]);
        acc.x += (h0.x + h1.x) + (h2.x + h3.x);
        acc.y += (h0.y + h1.y) + (h2.y + h3.y);
    }
    for (; j < m; j++) {
        int e = __ldg(ep + j);
        float2 hh = ldg_h2f2(&g_H2[(long)e * 32 + lane]);
        acc.x += hh.x;  acc.y += hh.y;
    }

    float2 o = make_float2(fmaxf(acc.x * dd, 0.0f), fmaxf(acc.y * dd, 0.0f));
    *(float2*)&out[(long)node * COUT_ + lane * 2] = o;
}

// ---------------------------------------------------------------------------
extern "C" void kernel_launch(void* const* d_in, const int* in_sizes, int n_in,
                              void* d_out, int out_size)
{
    const float* X    = (const float*)d_in[0];   // (N, 128)
    const float* W    = (const float*)d_in[1];   // (128, 64)
    const float* bias = (const float*)d_in[2];   // (64,)
    const int*   src  = (const int*)d_in[3];     // (E,)
    const int*   dst  = (const int*)d_in[4];     // (E,)
    float*       out  = (float*)d_out;           // (N, 64)

    const int n = in_sizes[0] / CIN_;
    const int E = in_sizes[3];
    const int nblk = (n + SCAN_C - 1) / SCAN_C;

    const int NG = (n + 127) / 128;          // gemm tiles
    const int NF = (E + 1023) / 1024;        // fill chunks

    degpos_kernel<<<(E + 1023) / 1024, 256>>>(dst, E);
    scan_kernel<<<nblk, 256>>>(n);
    gemmfill_kernel<<<NG + NF, 256>>>(X, W, bias, src, dst, n, E, NG);
    gather_kernel<<<(int)(((long)n * 32 + 255) / 256), 256>>>(out, n, E);
}

// round 12
// speedup vs baseline: 1.4674x; 1.0576x over previous
#include <cuda_runtime.h>
#include <cuda_fp16.h>

#define NMAX   100000
#define EMAX   1600000
#define CIN_   128
#define COUT_  64
#define SCAN_C 1024
#define NBLK_MAX 128

// Scratch (device globals — no allocation allowed).
// Invariants at entry (restored each call; static zero-init on first call):
//   g_deg == 0, g_scan_cnt == 0.
__device__ __half2 g_H2[NMAX * (COUT_ / 2)];   // Hs = (X@W+b)*dinv, fp16
__device__ float   g_dinv[NMAX];
__device__ int     g_deg[NMAX];
__device__ int     g_rowoff[NMAX];             // block-local exclusive prefix
__device__ int     g_boff[NBLK_MAX];           // per-1024-chunk global offset
__device__ int     g_bsum[NBLK_MAX];
__device__ int     g_pos[EMAX];
__device__ int     g_edge[EMAX];               // src only, CSR by dst
__device__ int     g_scan_cnt;

// ---------------------------------------------------------------------------
// 1) degree count + slot record, 4 edges/thread
// ---------------------------------------------------------------------------
__global__ __launch_bounds__(256) void degpos_kernel(const int* __restrict__ dst, int E) {
    int base = (blockIdx.x * 256 + threadIdx.x) * 4;
    if (base + 3 < E) {
        int4 d = *(const int4*)(dst + base);
        int4 p;
        p.x = atomicAdd(&g_deg[d.x], 1);
        p.y = atomicAdd(&g_deg[d.y], 1);
        p.z = atomicAdd(&g_deg[d.z], 1);
        p.w = atomicAdd(&g_deg[d.w], 1);
        *(int4*)(g_pos + base) = p;
    } else {
        for (int i = base; i < E; i++)
            g_pos[i] = atomicAdd(&g_deg[dst[i]], 1);
    }
}

// ---------------------------------------------------------------------------
// 2) scan: block-local exclusive prefix of deg, dinv=rsqrt(1+deg), deg:=0;
//    last-finishing block scans the <=128 block sums into g_boff.
// ---------------------------------------------------------------------------
__global__ __launch_bounds__(256) void scan_kernel(int n) {
    __shared__ int wsum[8];
    __shared__ int is_last;
    const int b    = blockIdx.x;
    const int base = b * SCAN_C + threadIdx.x * 4;
    const int lane = threadIdx.x & 31;
    const int warp = threadIdx.x >> 5;

    int v[4];
    #pragma unroll
    for (int i = 0; i < 4; i++) {
        int idx = base + i;
        v[i] = (idx < n) ? g_deg[idx] : 0;
        if (idx < n) {
            g_dinv[idx] = rsqrtf(1.0f + (float)v[i]);
            g_deg[idx]  = 0;                    // restore invariant
        }
    }
    int tsum = v[0] + v[1] + v[2] + v[3];

    int x = tsum;
    #pragma unroll
    for (int off = 1; off < 32; off <<= 1) {
        int y = __shfl_up_sync(0xFFFFFFFFu, x, off);
        if (lane >= off) x += y;
    }
    if (lane == 31) wsum[warp] = x;
    __syncthreads();
    if (threadIdx.x == 0) {
        int run = 0;
        #pragma unroll
        for (int w = 0; w < 8; w++) { int t = wsum[w]; wsum[w] = run; run += t; }
        g_bsum[b] = run;
    }
    __syncthreads();

    int run = wsum[warp] + x - tsum;
    #pragma unroll
    for (int i = 0; i < 4; i++) {
        int idx = base + i;
        if (idx < n) g_rowoff[idx] = run;
        run += v[i];
    }

    if (threadIdx.x == 0) {
        __threadfence();
        int old = atomicAdd(&g_scan_cnt, 1);
        is_last = (old == (int)gridDim.x - 1);
    }
    __syncthreads();
    if (is_last) {
        __threadfence();
        __shared__ int sp[NBLK_MAX];
        const int t = threadIdx.x;
        const int nblk = gridDim.x;
        if (t < NBLK_MAX) sp[t] = (t < nblk) ? g_bsum[t] : 0;
        __syncthreads();
        #pragma unroll
        for (int s = 1; s < NBLK_MAX; s <<= 1) {
            int vv = 0;
            if (t < NBLK_MAX && t >= s) vv = sp[t - s];
            __syncthreads();
            if (t < NBLK_MAX) sp[t] += vv;
            __syncthreads();
        }
        if (t < nblk) g_boff[t] = (t == 0) ? 0 : sp[t - 1];
        if (t == 0) g_scan_cnt = 0;             // restore invariant
    }
}

// ---------------------------------------------------------------------------
// 3) fused GEMM + CSR fill, role split by block (R11 winner, unchanged)
// ---------------------------------------------------------------------------
#define FMA2(d, a, b) asm("fma.rn.f32x2 %0, %1, %2, %3;" \
                          : "=l"(d) : "l"(a), "l"(b), "l"(d))

__global__ __launch_bounds__(256) void gemmfill_kernel(
    const float* __restrict__ X, const float* __restrict__ W,
    const float* __restrict__ bias,
    const int* __restrict__ src, const int* __restrict__ dst,
    int n, int E, int NG)
{
    const int tid = threadIdx.x;

    if (blockIdx.x >= NG) {
        // ---- fill role, 4 edges/thread ----
        int cid  = blockIdx.x - NG;
        int base = (cid * 256 + tid) * 4;
        if (base + 3 < E) {
            int4 s = *(const int4*)(src + base);
            int4 d = *(const int4*)(dst + base);
            int4 p = *(const int4*)(g_pos + base);
            int o0 = g_rowoff[d.x] + g_boff[d.x >> 10] + p.x;
            int o1 = g_rowoff[d.y] + g_boff[d.y >> 10] + p.y;
            int o2 = g_rowoff[d.z] + g_boff[d.z >> 10] + p.z;
            int o3 = g_rowoff[d.w] + g_boff[d.w >> 10] + p.w;
            g_edge[o0] = s.x;
            g_edge[o1] = s.y;
            g_edge[o2] = s.z;
            g_edge[o3] = s.w;
        } else {
            for (int i = base; i < E; i++) {
                int d = dst[i];
                g_edge[g_rowoff[d] + g_boff[d >> 10] + g_pos[i]] = src[i];
            }
        }
        return;
    }

    // ---- GEMM role ----
    __shared__ float2 Xs2[16][130];
    __shared__ float  Ws[16][64];

    const int tcol = tid & 15;
    const int trow = tid >> 4;
    const int row0 = blockIdx.x * 128;

    unsigned long long acc[8][2];
    #pragma unroll
    for (int r = 0; r < 8; r++) { acc[r][0] = 0ull; acc[r][1] = 0ull; }

    for (int k0 = 0; k0 < CIN_; k0 += 16) {
        #pragma unroll
        for (int p = 0; p < 2; p++) {
            int r  = p * 64 + (tid >> 2);
            int kq = tid & 3;
            int rr = row0 + r;
            const float* xp = X + (long)(rr < n ? rr : 0) * CIN_ + k0 + kq * 4;
            float4 v = *(const float4*)xp;
            Xs2[kq * 4 + 0][r] = make_float2(v.x, v.x);
            Xs2[kq * 4 + 1][r] = make_float2(v.y, v.y);
            Xs2[kq * 4 + 2][r] = make_float2(v.z, v.z);
            Xs2[kq * 4 + 3][r] = make_float2(v.w, v.w);
        }
        {
            int k    = tid >> 4;
            int colq = tid & 15;
            float4 v = *(const float4*)(W + (long)(k0 + k) * COUT_ + colq * 4);
            *(float4*)&Ws[k][colq * 4] = v;
        }
        __syncthreads();

        #pragma unroll
        for (int kk = 0; kk < 16; kk++) {
            ulonglong2 a01 = *(const ulonglong2*)&Xs2[kk][trow * 8 + 0];
            ulonglong2 a23 = *(const ulonglong2*)&Xs2[kk][trow * 8 + 2];
            ulonglong2 a45 = *(const ulonglong2*)&Xs2[kk][trow * 8 + 4];
            ulonglong2 a67 = *(const ulonglong2*)&Xs2[kk][trow * 8 + 6];
            ulonglong2 b   = *(const ulonglong2*)&Ws[kk][tcol * 4];
            FMA2(acc[0][0], a01.x, b.x);  FMA2(acc[0][1], a01.x, b.y);
            FMA2(acc[1][0], a01.y, b.x);  FMA2(acc[1][1], a01.y, b.y);
            FMA2(acc[2][0], a23.x, b.x);  FMA2(acc[2][1], a23.x, b.y);
            FMA2(acc[3][0], a23.y, b.x);  FMA2(acc[3][1], a23.y, b.y);
            FMA2(acc[4][0], a45.x, b.x);  FMA2(acc[4][1], a45.x, b.y);
            FMA2(acc[5][0], a45.y, b.x);  FMA2(acc[5][1], a45.y, b.y);
            FMA2(acc[6][0], a67.x, b.x);  FMA2(acc[6][1], a67.x, b.y);
            FMA2(acc[7][0], a67.y, b.x);  FMA2(acc[7][1], a67.y, b.y);
        }
        __syncthreads();
    }

    float2 bb0 = *(const float2*)(bias + tcol * 4);
    float2 bb1 = *(const float2*)(bias + tcol * 4 + 2);
    #pragma unroll
    for (int r = 0; r < 8; r++) {
        int row = row0 + trow * 8 + r;
        if (row < n) {
            float di = g_dinv[row];
            float2 lo = *(const float2*)&acc[r][0];
            float2 hi = *(const float2*)&acc[r][1];
            __half2 h0 = __floats2half2_rn((lo.x + bb0.x) * di, (lo.y + bb0.y) * di);
            __half2 h1 = __floats2half2_rn((hi.x + bb1.x) * di, (hi.y + bb1.y) * di);
            g_H2[(long)row * 32 + tcol * 2]     = h0;
            g_H2[(long)row * 32 + tcol * 2 + 1] = h1;
        }
    }
}

// ---------------------------------------------------------------------------
// 4) gather: one warp per node, one half2 per lane (64 cols).
//    Issue-optimized: 32-bit edge offsets (single IMAD.WIDE addressing) and
//    fp16 HADD2 pairwise-tree pre-reduction (tree of 4) before fp32 accum.
//    out[d] = relu( dinv[d] * ( Hs[d] + sum_e Hs[src] ) )
// ---------------------------------------------------------------------------
__global__ __launch_bounds__(256) void gather_kernel(float* __restrict__ out,
                                                     int n, int E) {
    int node = (blockIdx.x * 256 + threadIdx.x) >> 5;
    if (node >= n) return;
    int lane = threadIdx.x & 31;

    float dd = g_dinv[node];
    int   r0 = g_rowoff[node] + g_boff[node >> 10];
    int   r1 = (node + 1 < n) ? (g_rowoff[node + 1] + g_boff[(node + 1) >> 10]) : E;
    int   m  = r1 - r0;

    const __half2* hb = g_H2 + lane;                 // per-lane base
    float2 acc = __half22float2(__ldg(hb + ((unsigned)node << 5)));

    const int* ep = &g_edge[r0];
    int j = 0;
    for (; j + 8 <= m; j += 8) {
        unsigned e0 = (unsigned)__ldg(ep + j)     << 5;
        unsigned e1 = (unsigned)__ldg(ep + j + 1) << 5;
        unsigned e2 = (unsigned)__ldg(ep + j + 2) << 5;
        unsigned e3 = (unsigned)__ldg(ep + j + 3) << 5;
        unsigned e4 = (unsigned)__ldg(ep + j + 4) << 5;
        unsigned e5 = (unsigned)__ldg(ep + j + 5) << 5;
        unsigned e6 = (unsigned)__ldg(ep + j + 6) << 5;
        unsigned e7 = (unsigned)__ldg(ep + j + 7) << 5;
        __half2 a0 = __ldg(hb + e0), a1 = __ldg(hb + e1);
        __half2 a2 = __ldg(hb + e2), a3 = __ldg(hb + e3);
        __half2 a4 = __ldg(hb + e4), a5 = __ldg(hb + e5);
        __half2 a6 = __ldg(hb + e6), a7 = __ldg(hb + e7);
        __half2 s01 = __hadd2(a0, a1), s23 = __hadd2(a2, a3);
        __half2 s45 = __hadd2(a4, a5), s67 = __hadd2(a6, a7);
        __half2 s03 = __hadd2(s01, s23), s47 = __hadd2(s45, s67);
        float2 f0 = __half22float2(s03);
        float2 f1 = __half22float2(s47);
        acc.x += f0.x + f1.x;
        acc.y += f0.y + f1.y;
    }
    if (j + 4 <= m) {
        unsigned e0 = (unsigned)__ldg(ep + j)     << 5;
        unsigned e1 = (unsigned)__ldg(ep + j + 1) << 5;
        unsigned e2 = (unsigned)__ldg(ep + j + 2) << 5;
        unsigned e3 = (unsigned)__ldg(ep + j + 3) << 5;
        __half2 a0 = __ldg(hb + e0), a1 = __ldg(hb + e1);
        __half2 a2 = __ldg(hb + e2), a3 = __ldg(hb + e3);
        __half2 s01 = __hadd2(a0, a1), s23 = __hadd2(a2, a3);
        float2 f0 = __half22float2(s01);
        float2 f1 = __half22float2(s23);
        acc.x += f0.x + f1.x;
        acc.y += f0.y + f1.y;
        j += 4;
    }
    for (; j < m; j++) {
        unsigned e = (unsigned)__ldg(ep + j) << 5;
        float2 hh = __half22float2(__ldg(hb + e));
        acc.x += hh.x;  acc.y += hh.y;
    }

    float2 o = make_float2(fmaxf(acc.x * dd, 0.0f), fmaxf(acc.y * dd, 0.0f));
    *(float2*)&out[(long)node * COUT_ + lane * 2] = o;
}

// ---------------------------------------------------------------------------
extern "C" void kernel_launch(void* const* d_in, const int* in_sizes, int n_in,
                              void* d_out, int out_size)
{
    const float* X    = (const float*)d_in[0];   // (N, 128)
    const float* W    = (const float*)d_in[1];   // (128, 64)
    const float* bias = (const float*)d_in[2];   // (64,)
    const int*   src  = (const int*)d_in[3];     // (E,)
    const int*   dst  = (const int*)d_in[4];     // (E,)
    float*       out  = (float*)d_out;           // (N, 64)

    const int n = in_sizes[0] / CIN_;
    const int E = in_sizes[3];
    const int nblk = (n + SCAN_C - 1) / SCAN_C;

    const int NG = (n + 127) / 128;          // gemm tiles
    const int NF = (E + 1023) / 1024;        // fill chunks

    degpos_kernel<<<(E + 1023) / 1024, 256>>>(dst, E);
    scan_kernel<<<nblk, 256>>>(n);
    gemmfill_kernel<<<NG + NF, 256>>>(X, W, bias, src, dst, n, E, NG);
    gather_kernel<<<(int)(((long)n * 32 + 255) / 256), 256>>>(out, n, E);
}